// round 15
// baseline (speedup 1.0000x reference)
#include <cuda_runtime.h>

#define BB 8
#define CC 32
#define HH 384
#define WW 768
#define HW  (HH * WW)
#define CHW ((size_t)CC * HH * WW)
#define CPI 4                        // channels per iteration (best measured)
#define NROW (BB * HH)               // 3072 row-tiles
#define NBLK 296                     // 148 SMs x 2 resident blocks (regs=40, 768 thr)

__global__ __launch_bounds__(768)
void disparity_warp_k15(const float* __restrict__ src,
                        const float* __restrict__ disp,
                        float* __restrict__ out) {
    __shared__ float tmp[2][CPI][WW];   // double-buffered vert-interpolated rows

    const int w = threadIdx.x;          // 0..767

    for (int tile = blockIdx.x; tile < NROW; tile += NBLK) {
        const int h = tile % HH;
        const int b = tile / HH;

        // ---- vertical coords: uniform per row-tile ----
        const float iy  = (float)h * (384.0f / 383.0f) - 0.5f;
        const float y0f = floorf(iy);
        const float fy  = iy - y0f;
        const int   y0  = (int)y0f, y1 = y0 + 1;
        const float wy0 = (1.0f - fy) * (((y0 >= 0) & (y0 < HH)) ? 1.0f : 0.0f);
        const float wy1 = fy          * (((y1 >= 0) & (y1 < HH)) ? 1.0f : 0.0f);
        const int   cy0 = min(max(y0, 0), HH - 1);
        const int   cy1 = min(max(y1, 0), HH - 1);

        // ---- horizontal coords: per-thread (disp read once -> streaming) ----
        const float d   = __ldcs(disp + (size_t)(b * HH + h) * WW + w);
        const float ix  = ((float)w - d) * (768.0f / 767.0f) - 0.5f;
        const float x0f = floorf(ix);
        const float fx  = ix - x0f;
        const int   x0  = (int)x0f, x1 = x0 + 1;
        const float wx0 = (1.0f - fx) * (((x0 >= 0) & (x0 < WW)) ? 1.0f : 0.0f);
        const float wx1 = fx          * (((x1 >= 0) & (x1 < WW)) ? 1.0f : 0.0f);
        const int   cx0 = min(max(x0, 0), WW - 1);
        const int   cx1 = min(max(x1, 0), WW - 1);

        const float* r0 = src + (size_t)b * CHW + (size_t)cy0 * WW + w;
        const float* r1 = src + (size_t)b * CHW + (size_t)cy1 * WW + w;
        float* ob = out + (size_t)b * CHW + (size_t)h * WW + w;

        #pragma unroll
        for (int it = 0; it < CC / CPI; ++it) {
            const int buf = it & 1;

            // phase 1: vertical interp, fully coalesced (8 LDG in flight)
            float v[CPI];
            #pragma unroll
            for (int cc = 0; cc < CPI; ++cc) {
                const int c = it * CPI + cc;
                const float a0 = r0[(size_t)c * HW];
                const float a1 = r1[(size_t)c * HW];
                v[cc] = a0 * wy0 + a1 * wy1;
            }
            #pragma unroll
            for (int cc = 0; cc < CPI; ++cc)
                tmp[buf][cc][w] = v[cc];

            __syncthreads();

            // phase 2: horizontal interp from shared row; streaming stores
            // keep the reusable src rows resident in L2.
            #pragma unroll
            for (int cc = 0; cc < CPI; ++cc) {
                const int c = it * CPI + cc;
                const float t = tmp[buf][cc][cx0] * wx0 + tmp[buf][cc][cx1] * wx1;
                __stcs(ob + (size_t)c * HW, t);
            }
            // double buffer: reuse separated by the next iteration's barrier
            // (holds across tile boundaries too: writes to a buffer follow a
            //  barrier that all readers of that buffer have already passed).
        }
    }
}

extern "C" void kernel_launch(void* const* d_in, const int* in_sizes, int n_in,
                              void* d_out, int out_size) {
    const float* src  = (const float*)d_in[0];
    const float* disp = (const float*)d_in[1];
    float* out = (float*)d_out;

    disparity_warp_k15<<<NBLK, 768>>>(src, disp, out);
}

// round 17
// speedup vs baseline: 1.0914x; 1.0914x over previous
#include <cuda_runtime.h>

#define BB 8
#define CC 32
#define HH 384
#define WW 768
#define HW  (HH * WW)
#define CHW ((size_t)CC * HH * WW)
#define CPI 4                        // channels per iteration (measured optimum)

__global__ __launch_bounds__(768)
void disparity_warp_k17(const float* __restrict__ src,
                        const float* __restrict__ disp,
                        float* __restrict__ out) {
    __shared__ float tmp[2][CPI][WW];   // double-buffered vert-interpolated rows

    const int w = threadIdx.x;          // 0..767
    const int h = blockIdx.x % HH;
    const int b = blockIdx.x / HH;

    // ---- vertical coords: uniform per block ----
    const float iy  = (float)h * (384.0f / 383.0f) - 0.5f;
    const float y0f = floorf(iy);
    const float fy  = iy - y0f;
    const int   y0  = (int)y0f, y1 = y0 + 1;
    const float wy0 = (1.0f - fy) * (((y0 >= 0) & (y0 < HH)) ? 1.0f : 0.0f);
    const float wy1 = fy          * (((y1 >= 0) & (y1 < HH)) ? 1.0f : 0.0f);
    const int   cy0 = min(max(y0, 0), HH - 1);
    const int   cy1 = min(max(y1, 0), HH - 1);

    // ---- horizontal coords: per-thread (disp read once -> streaming load) ----
    const float d   = __ldcs(disp + (size_t)(b * HH + h) * WW + w);
    const float ix  = ((float)w - d) * (768.0f / 767.0f) - 0.5f;
    const float x0f = floorf(ix);
    const float fx  = ix - x0f;
    const int   x0  = (int)x0f, x1 = x0 + 1;
    const float wx0 = (1.0f - fx) * (((x0 >= 0) & (x0 < WW)) ? 1.0f : 0.0f);
    const float wx1 = fx          * (((x1 >= 0) & (x1 < WW)) ? 1.0f : 0.0f);
    const int   cx0 = min(max(x0, 0), WW - 1);
    const int   cx1 = min(max(x1, 0), WW - 1);

    const float* r0 = src + (size_t)b * CHW + (size_t)cy0 * WW + w;  // coalesced
    const float* r1 = src + (size_t)b * CHW + (size_t)cy1 * WW + w;  // coalesced
    float* ob = out + (size_t)b * CHW + (size_t)h * WW + w;

    #pragma unroll
    for (int it = 0; it < CC / CPI; ++it) {
        const int buf = it & 1;

        // phase 1: vertical interp, fully coalesced (8 LDG in flight)
        float v[CPI];
        #pragma unroll
        for (int cc = 0; cc < CPI; ++cc) {
            const int c = it * CPI + cc;
            const float a0 = r0[(size_t)c * HW];
            const float a1 = r1[(size_t)c * HW];
            v[cc] = a0 * wy0 + a1 * wy1;
        }
        #pragma unroll
        for (int cc = 0; cc < CPI; ++cc)
            tmp[buf][cc][w] = v[cc];

        __syncthreads();

        // phase 2: horizontal interp from shared row; streaming (evict-first)
        // stores keep the reusable src rows resident in L2.
        #pragma unroll
        for (int cc = 0; cc < CPI; ++cc) {
            const int c = it * CPI + cc;
            const float t = tmp[buf][cc][cx0] * wx0 + tmp[buf][cc][cx1] * wx1;
            __stcs(ob + (size_t)c * HW, t);
        }
        // double buffer: smem reuse separated by the next iteration's barrier
    }
}

extern "C" void kernel_launch(void* const* d_in, const int* in_sizes, int n_in,
                              void* d_out, int out_size) {
    const float* src  = (const float*)d_in[0];
    const float* disp = (const float*)d_in[1];
    float* out = (float*)d_out;

    disparity_warp_k17<<<BB * HH, 768>>>(src, disp, out);
}